// round 2
// baseline (speedup 1.0000x reference)
#include <cuda_runtime.h>
#include <cstdint>
#include <math.h>

// ---------------------------------------------------------------------------
// ImprovedGraphLSTMCell  (N=8192, K=8, H=512, X=512)
//
//  wf_x  = x @ W_f                                  [N,H]
//  iou   = x @ W_iou + (sum_k h_two) @ U_iou + b    [N,3H]
//  f     = sigmoid(wf_x + h_two @ U_f + b_f)        [N,K,H]   (never stored)
//  c_agg = sum_k f * c_mail                         [N,H]
//  c = sig(i)*tanh(u) + c_agg ; h = sig(o)*tanh(c)
//
// All GEMMs: tf32 mma.sync m16n8k8, fp32 accumulate, rna-rounded operands.
// ---------------------------------------------------------------------------

namespace {
constexpr int Nn  = 8192;
constexpr int Kmb = 8;
constexpr int Hh  = 512;
constexpr int Xx  = 512;
constexpr int NK  = Nn * Kmb;     // 65536
constexpr int H2v = 2 * Hh;       // 1024
constexpr int H3v = 3 * Hh;       // 1536

constexpr int BM = 128, BN = 128, BK = 32;
constexpr int APAD = 4, BPAD = 4;
}

// Scratch (device globals — no allocation allowed in kernel_launch)
__device__ float g_wfx[Nn * Hh];            // 16 MB
__device__ float g_iou[Nn * H3v];           // 48 MB
__device__ float g_hsum2[Nn * H2v];         // 64 MB
__device__ float g_cagg[Nn * Hh];           // 16 MB

// cvt to tf32: destination is a .b32 register (bit-pattern type) — "=r", not "=f".
__device__ __forceinline__ float to_tf32(float x) {
    uint32_t r;
    asm("cvt.rna.tf32.f32 %0, %1;" : "=r"(r) : "f"(x));
    return __uint_as_float(r);
}

__device__ __forceinline__ void mma8(float c[4],
                                     uint32_t a0, uint32_t a1, uint32_t a2, uint32_t a3,
                                     uint32_t b0, uint32_t b1) {
    asm volatile(
        "mma.sync.aligned.m16n8k8.row.col.f32.tf32.tf32.f32 "
        "{%0,%1,%2,%3}, {%4,%5,%6,%7}, {%8,%9}, {%0,%1,%2,%3};\n"
        : "+f"(c[0]), "+f"(c[1]), "+f"(c[2]), "+f"(c[3])
        : "r"(a0), "r"(a1), "r"(a2), "r"(a3), "r"(b0), "r"(b1));
}

__device__ __forceinline__ float sigmoidf_(float x) {
    return 1.f / (1.f + __expf(-x));
}

// ---------------------------------------------------------------------------
// Kernel 1: mailbox pre-reduction routed by edge label.
//   hsum2[n, h]      = sum_k (1-e[n,k]) * h_mail[n,k,h]
//   hsum2[n, H+h]    = sum_k    e[n,k]  * h_mail[n,k,h]
// ---------------------------------------------------------------------------
__global__ void prep_hsum(const float* __restrict__ hm, const float* __restrict__ el) {
    int idx = blockIdx.x * blockDim.x + threadIdx.x;
    if (idx >= Nn * Hh) return;
    int n = idx >> 9;
    int h = idx & 511;
    const float* hp = hm + (size_t)n * Kmb * Hh + h;
    const float* ep = el + n * Kmb;
    float s0 = 0.f, s1 = 0.f;
#pragma unroll
    for (int k = 0; k < Kmb; k++) {
        float e = ep[k];
        float v = hp[(size_t)k * Hh];
        float ev = e * v;
        s1 += ev;
        s0 += v - ev;
    }
    g_hsum2[(size_t)n * H2v + h]      = s0;
    g_hsum2[(size_t)n * H2v + Hh + h] = s1;
}

// ---------------------------------------------------------------------------
// Generic tf32 GEMM: C[M,Nc] (+)= A[M,Kd] @ B[Kd,Nc]
// 256 threads, BM=BN=128, BK=32, warp grid 2x4, warp tile 64x32.
// M % 128 == 0, Kd % 32 == 0, Nc % 128 == 0 (all true for our shapes).
// ---------------------------------------------------------------------------
template <bool ACCUM>
__global__ void __launch_bounds__(256) gemm128(const float* __restrict__ A,
                                               const float* __restrict__ B,
                                               float* __restrict__ C,
                                               int M, int Kd, int Nc) {
    __shared__ float sA[BM][BK + APAD];
    __shared__ float sB[BK][BN + BPAD];

    const int tid  = threadIdx.x;
    const int lane = tid & 31;
    const int wid  = tid >> 5;
    const int g    = lane >> 2;     // groupID
    const int tg   = lane & 3;      // threadID in group
    const int wr   = wid >> 2;      // warp row 0..1
    const int wc   = wid & 3;       // warp col 0..3
    const int m0   = blockIdx.x * BM;
    const int n0   = blockIdx.y * BN;

    float acc[4][4][4];
#pragma unroll
    for (int a = 0; a < 4; a++)
#pragma unroll
        for (int b = 0; b < 4; b++)
#pragma unroll
            for (int c = 0; c < 4; c++) acc[a][b][c] = 0.f;

    float4 ra[4], rb[4];

    const int arow = tid >> 3;            // 0..31 (+32*i)
    const int acol = (tid & 7) << 2;      // 0..28
    const int brow = tid >> 5;            // 0..7  (+8*i)
    const int bcol = (tid & 31) << 2;     // 0..124

#define LOAD_A(kt)                                                                 \
    {                                                                              \
        const float* Ap = A + (size_t)(m0 + arow) * Kd + (kt) * BK + acol;         \
        _Pragma("unroll") for (int i = 0; i < 4; i++)                              \
            ra[i] = *(const float4*)(Ap + (size_t)(i * 32) * Kd);                  \
    }
#define LOAD_B(kt)                                                                 \
    {                                                                              \
        const float* Bp = B + (size_t)((kt) * BK + brow) * Nc + n0 + bcol;         \
        _Pragma("unroll") for (int i = 0; i < 4; i++)                              \
            rb[i] = *(const float4*)(Bp + (size_t)(i * 8) * Nc);                   \
    }
#define STORE_TILES()                                                              \
    {                                                                              \
        _Pragma("unroll") for (int i = 0; i < 4; i++) {                            \
            float* p = &sA[arow + i * 32][acol];                                   \
            p[0] = to_tf32(ra[i].x); p[1] = to_tf32(ra[i].y);                      \
            p[2] = to_tf32(ra[i].z); p[3] = to_tf32(ra[i].w);                      \
        }                                                                          \
        _Pragma("unroll") for (int i = 0; i < 4; i++) {                            \
            float* p = &sB[brow + i * 8][bcol];                                    \
            p[0] = to_tf32(rb[i].x); p[1] = to_tf32(rb[i].y);                      \
            p[2] = to_tf32(rb[i].z); p[3] = to_tf32(rb[i].w);                      \
        }                                                                          \
    }
#define COMPUTE_TILE()                                                             \
    {                                                                              \
        _Pragma("unroll") for (int ks = 0; ks < 4; ks++) {                         \
            const int k8 = ks * 8;                                                 \
            uint32_t af[4][4], bfr[4][2];                                          \
            _Pragma("unroll") for (int mi = 0; mi < 4; mi++) {                     \
                const int r = wr * 64 + mi * 16;                                   \
                af[mi][0] = __float_as_uint(sA[r + g][k8 + tg]);                   \
                af[mi][1] = __float_as_uint(sA[r + g + 8][k8 + tg]);               \
                af[mi][2] = __float_as_uint(sA[r + g][k8 + tg + 4]);               \
                af[mi][3] = __float_as_uint(sA[r + g + 8][k8 + tg + 4]);           \
            }                                                                      \
            _Pragma("unroll") for (int ni = 0; ni < 4; ni++) {                     \
                const int cb = wc * 32 + ni * 8 + g;                               \
                bfr[ni][0] = __float_as_uint(sB[k8 + tg][cb]);                     \
                bfr[ni][1] = __float_as_uint(sB[k8 + tg + 4][cb]);                 \
            }                                                                      \
            _Pragma("unroll") for (int mi = 0; mi < 4; mi++)                       \
                _Pragma("unroll") for (int ni = 0; ni < 4; ni++)                   \
                    mma8(acc[mi][ni], af[mi][0], af[mi][1], af[mi][2], af[mi][3],  \
                         bfr[ni][0], bfr[ni][1]);                                  \
        }                                                                          \
    }

    const int KT = Kd / BK;
    LOAD_A(0); LOAD_B(0);
    STORE_TILES();
    __syncthreads();
    for (int kt = 1; kt < KT; kt++) {
        LOAD_A(kt); LOAD_B(kt);
        COMPUTE_TILE();
        __syncthreads();
        STORE_TILES();
        __syncthreads();
    }
    COMPUTE_TILE();

#pragma unroll
    for (int mi = 0; mi < 4; mi++) {
#pragma unroll
        for (int ni = 0; ni < 4; ni++) {
            int r0 = m0 + wr * 64 + mi * 16 + g;
            int c0 = n0 + wc * 32 + ni * 8 + 2 * tg;
            float* p0 = C + (size_t)r0 * Nc + c0;
            float* p1 = C + (size_t)(r0 + 8) * Nc + c0;
            if (ACCUM) {
                float2 o0 = *(float2*)p0, o1 = *(float2*)p1;
                o0.x += acc[mi][ni][0]; o0.y += acc[mi][ni][1];
                o1.x += acc[mi][ni][2]; o1.y += acc[mi][ni][3];
                *(float2*)p0 = o0;
                *(float2*)p1 = o1;
            } else {
                *(float2*)p0 = make_float2(acc[mi][ni][0], acc[mi][ni][1]);
                *(float2*)p1 = make_float2(acc[mi][ni][2], acc[mi][ni][3]);
            }
        }
    }
#undef LOAD_A
#undef LOAD_B
#undef STORE_TILES
#undef COMPUTE_TILE
}

// ---------------------------------------------------------------------------
// Fused F GEMM: rows = (n,k) pairs (NK=65536), contraction over 2H=1024 where
// A[row, 0:H] = (1-e)*h_mail[row], A[row, H:2H] = e*h_mail[row] (built in the
// A loader — h_two is never materialized). Epilogue:
//   f = sigmoid(acc + wf_x[n] + b_f);  c_agg[n] = sum_{k in tile} f*c_mail[row]
// BM=128 = 16 whole nodes, so the k-reduction is warp-shuffle local, no atomics.
// ---------------------------------------------------------------------------
__global__ void __launch_bounds__(256) fgemm(const float* __restrict__ hm,
                                             const float* __restrict__ el,
                                             const float* __restrict__ cm,
                                             const float* __restrict__ Uf,
                                             const float* __restrict__ bfv) {
    __shared__ float sA[BM][BK + APAD];
    __shared__ float sB[BK][BN + BPAD];

    const int tid  = threadIdx.x;
    const int lane = tid & 31;
    const int wid  = tid >> 5;
    const int g    = lane >> 2;
    const int tg   = lane & 3;
    const int wr   = wid >> 2;
    const int wc   = wid & 3;
    const int m0   = blockIdx.x * BM;   // row tile over NK
    const int n0   = blockIdx.y * BN;   // col tile over H

    float acc[4][4][4];
#pragma unroll
    for (int a = 0; a < 4; a++)
#pragma unroll
        for (int b = 0; b < 4; b++)
#pragma unroll
            for (int c = 0; c < 4; c++) acc[a][b][c] = 0.f;

    float4 ra[4], rb[4];
    const int arow = tid >> 3;
    const int acol = (tid & 7) << 2;
    const int brow = tid >> 5;
    const int bcol = (tid & 31) << 2;
    const int Nc = Hh;    // 512
    const int Kd = H2v;   // 1024

#define LOAD_A_ROUTED(kt)                                                          \
    {                                                                              \
        const int k0   = (kt) * BK;                                                \
        const int hcol = (k0 & (Hh - 1)) + acol;                                   \
        const bool hi  = (k0 >= Hh);                                               \
        _Pragma("unroll") for (int i = 0; i < 4; i++) {                            \
            const int grow = m0 + arow + i * 32;                                   \
            const float e  = __ldg(el + grow);                                     \
            const float s  = hi ? e : (1.f - e);                                   \
            float4 v = *(const float4*)(hm + (size_t)grow * Hh + hcol);            \
            ra[i].x = s * v.x; ra[i].y = s * v.y;                                  \
            ra[i].z = s * v.z; ra[i].w = s * v.w;                                  \
        }                                                                          \
    }
#define LOAD_B2(kt)                                                                \
    {                                                                              \
        const float* Bp = Uf + (size_t)((kt) * BK + brow) * Nc + n0 + bcol;        \
        _Pragma("unroll") for (int i = 0; i < 4; i++)                              \
            rb[i] = *(const float4*)(Bp + (size_t)(i * 8) * Nc);                   \
    }
#define STORE_TILES2()                                                             \
    {                                                                              \
        _Pragma("unroll") for (int i = 0; i < 4; i++) {                            \
            float* p = &sA[arow + i * 32][acol];                                   \
            p[0] = to_tf32(ra[i].x); p[1] = to_tf32(ra[i].y);                      \
            p[2] = to_tf32(ra[i].z); p[3] = to_tf32(ra[i].w);                      \
        }                                                                          \
        _Pragma("unroll") for (int i = 0; i < 4; i++) {                            \
            float* p = &sB[brow + i * 8][bcol];                                    \
            p[0] = to_tf32(rb[i].x); p[1] = to_tf32(rb[i].y);                      \
            p[2] = to_tf32(rb[i].z); p[3] = to_tf32(rb[i].w);                      \
        }                                                                          \
    }
#define COMPUTE_TILE2()                                                            \
    {                                                                              \
        _Pragma("unroll") for (int ks = 0; ks < 4; ks++) {                         \
            const int k8 = ks * 8;                                                 \
            uint32_t af[4][4], bfr[4][2];                                          \
            _Pragma("unroll") for (int mi = 0; mi < 4; mi++) {                     \
                const int r = wr * 64 + mi * 16;                                   \
                af[mi][0] = __float_as_uint(sA[r + g][k8 + tg]);                   \
                af[mi][1] = __float_as_uint(sA[r + g + 8][k8 + tg]);               \
                af[mi][2] = __float_as_uint(sA[r + g][k8 + tg + 4]);               \
                af[mi][3] = __float_as_uint(sA[r + g + 8][k8 + tg + 4]);           \
            }                                                                      \
            _Pragma("unroll") for (int ni = 0; ni < 4; ni++) {                     \
                const int cb = wc * 32 + ni * 8 + g;                               \
                bfr[ni][0] = __float_as_uint(sB[k8 + tg][cb]);                     \
                bfr[ni][1] = __float_as_uint(sB[k8 + tg + 4][cb]);                 \
            }                                                                      \
            _Pragma("unroll") for (int mi = 0; mi < 4; mi++)                       \
                _Pragma("unroll") for (int ni = 0; ni < 4; ni++)                   \
                    mma8(acc[mi][ni], af[mi][0], af[mi][1], af[mi][2], af[mi][3],  \
                         bfr[ni][0], bfr[ni][1]);                                  \
        }                                                                          \
    }

    const int KT = Kd / BK;   // 32
    LOAD_A_ROUTED(0); LOAD_B2(0);
    STORE_TILES2();
    __syncthreads();
    for (int kt = 1; kt < KT; kt++) {
        LOAD_A_ROUTED(kt); LOAD_B2(kt);
        COMPUTE_TILE2();
        __syncthreads();
        STORE_TILES2();
        __syncthreads();
    }
    COMPUTE_TILE2();

    // Fused epilogue: f = sigmoid(acc + wf_x + b_f); reduce f*c_mail over k.
#pragma unroll
    for (int mi = 0; mi < 4; mi++) {
        const int rbase = m0 + wr * 64 + mi * 16;   // 16 rows = nodes nA, nA+1
        const int nA = rbase >> 3;
#pragma unroll
        for (int ni = 0; ni < 4; ni++) {
            const int gc = n0 + wc * 32 + ni * 8 + 2 * tg;
            const float b0 = bfv[gc], b1 = bfv[gc + 1];
            const float wA0 = g_wfx[(size_t)nA * Hh + gc];
            const float wA1 = g_wfx[(size_t)nA * Hh + gc + 1];
            const float wB0 = g_wfx[(size_t)(nA + 1) * Hh + gc];
            const float wB1 = g_wfx[(size_t)(nA + 1) * Hh + gc + 1];
            const int rA = rbase + g;
            const float2 cA = *(const float2*)(cm + (size_t)rA * Hh + gc);
            const float2 cB = *(const float2*)(cm + (size_t)(rA + 8) * Hh + gc);
            float v0 = sigmoidf_(acc[mi][ni][0] + wA0 + b0) * cA.x;
            float v1 = sigmoidf_(acc[mi][ni][1] + wA1 + b1) * cA.y;
            float v2 = sigmoidf_(acc[mi][ni][2] + wB0 + b0) * cB.x;
            float v3 = sigmoidf_(acc[mi][ni][3] + wB1 + b1) * cB.y;
            // sum over 8 rows of each node = lanes differing in bits 2..4
#pragma unroll
            for (int m = 4; m <= 16; m <<= 1) {
                v0 += __shfl_xor_sync(0xFFFFFFFFu, v0, m);
                v1 += __shfl_xor_sync(0xFFFFFFFFu, v1, m);
                v2 += __shfl_xor_sync(0xFFFFFFFFu, v2, m);
                v3 += __shfl_xor_sync(0xFFFFFFFFu, v3, m);
            }
            if (lane < 4) {
                *(float2*)(g_cagg + (size_t)nA * Hh + gc)       = make_float2(v0, v1);
                *(float2*)(g_cagg + (size_t)(nA + 1) * Hh + gc) = make_float2(v2, v3);
            }
        }
    }
#undef LOAD_A_ROUTED
#undef LOAD_B2
#undef STORE_TILES2
#undef COMPUTE_TILE2
}

// ---------------------------------------------------------------------------
// Final elementwise epilogue: gates + cell/hidden state.  out = [h ; c]
// ---------------------------------------------------------------------------
__global__ void final_ep(const float* __restrict__ biou, float* __restrict__ out) {
    int idx = blockIdx.x * blockDim.x + threadIdx.x;
    if (idx >= Nn * Hh) return;
    int n = idx >> 9;
    int h = idx & 511;
    const float* row = g_iou + (size_t)n * H3v;
    float iv = row[h] + biou[h];
    float ov = row[Hh + h] + biou[Hh + h];
    float uv = row[2 * Hh + h] + biou[2 * Hh + h];
    iv = sigmoidf_(iv);
    ov = sigmoidf_(ov);
    uv = tanhf(uv);
    float c = iv * uv + g_cagg[idx];
    out[idx]           = ov * tanhf(c);   // h
    out[Nn * Hh + idx] = c;               // c
}

// ---------------------------------------------------------------------------
extern "C" void kernel_launch(void* const* d_in, const int* in_sizes, int n_in,
                              void* d_out, int out_size) {
    const float* x    = (const float*)d_in[0];
    const float* hm   = (const float*)d_in[1];
    const float* cm   = (const float*)d_in[2];
    const float* el   = (const float*)d_in[3];
    const float* Wiou = (const float*)d_in[4];
    const float* Wf   = (const float*)d_in[5];
    const float* Uiou = (const float*)d_in[6];
    const float* Uf   = (const float*)d_in[7];
    const float* biou = (const float*)d_in[8];
    const float* bfv  = (const float*)d_in[9];
    float* out = (float*)d_out;

    float *p_wfx, *p_iou, *p_hsum2;
    cudaGetSymbolAddress((void**)&p_wfx, g_wfx);
    cudaGetSymbolAddress((void**)&p_iou, g_iou);
    cudaGetSymbolAddress((void**)&p_hsum2, g_hsum2);

    // 1) mailbox pre-reduction (feeds iou_mid GEMM)
    prep_hsum<<<(Nn * Hh + 255) / 256, 256>>>(hm, el);

    // 2) wf_x = x @ W_f
    {
        dim3 grid(Nn / BM, Hh / BN);
        gemm128<false><<<grid, 256>>>(x, Wf, p_wfx, Nn, Xx, Hh);
    }
    // 3) iou = x @ W_iou ; 4) iou += hsum2 @ U_iou
    {
        dim3 grid(Nn / BM, H3v / BN);
        gemm128<false><<<grid, 256>>>(x, Wiou, p_iou, Nn, Xx, H3v);
        gemm128<true><<<grid, 256>>>(p_hsum2, Uiou, p_iou, Nn, H2v, H3v);
    }
    // 5) fused f-gate GEMM + c_agg reduction (needs wf_x)
    {
        dim3 grid(NK / BM, Hh / BN);
        fgemm<<<grid, 256>>>(hm, el, cm, Uf, bfv);
    }
    // 6) gates + outputs
    final_ep<<<(Nn * Hh + 255) / 256, 256>>>(biou, out);
}